// round 3
// baseline (speedup 1.0000x reference)
#include <cuda_runtime.h>
#include <cuda_bf16.h>
#include <cstdint>

// MultiDense: out[i,j,l] = sum_k x[i,j,k] * params[inds[i], l, k] + params[inds[i], l, 128]
// I=8192, J=32, K=F=128, params row stride 129 (weight 128 + bias 1)
// NOTE: indices are int32 on device (JAX x64 disabled downcasts int64 -> int32).

constexpr int I_TOT = 8192;
constexpr int J_DIM = 32;
constexpr int F_DIM = 128;
constexpr int N_NODES = 4096;
constexpr int P_ROW = 129;                 // floats per output-feature row (128 w + 1 b)
constexpr int P_SZ  = F_DIM * P_ROW;       // 16512 floats per node
constexpr int X_SZ  = J_DIM * F_DIM;       // 4096 floats per item
constexpr int SMEM_FLOATS = P_SZ + X_SZ;   // 20608 floats = 82432 bytes

__global__ void __launch_bounds__(256, 2)
multidense_kernel(const float* __restrict__ x,
                  const int* __restrict__ inds,
                  const float* __restrict__ params,
                  float* __restrict__ out)
{
    extern __shared__ float smem[];
    float* ps = smem;            // [16512] gathered param block (row stride 129)
    float* xs = smem + P_SZ;     // [32*128] x tile, row-major [j][k]

    const int i    = blockIdx.x;
    const int tid  = threadIdx.x;

    int node = inds[i];
    node = min(max(node, 0), N_NODES - 1);   // defensive clamp (diagnostic, not load-bearing)

    // ---- stage params (float4 vectorized; base 16B-aligned: 16512 % 4 == 0) ----
    {
        const float4* src = reinterpret_cast<const float4*>(params + (size_t)node * P_SZ);
        float4* dst = reinterpret_cast<float4*>(ps);
        #pragma unroll 4
        for (int t = tid; t < P_SZ / 4; t += 256) dst[t] = src[t];
    }
    // ---- stage x tile ----
    {
        const float4* src = reinterpret_cast<const float4*>(x + (size_t)i * X_SZ);
        float4* dst = reinterpret_cast<float4*>(xs);
        #pragma unroll
        for (int t = tid; t < X_SZ / 4; t += 256) dst[t] = src[t];
    }
    __syncthreads();

    // ---- compute: warp w -> j in [4w, 4w+4); lane -> l = lane + 32c, c in [0,4) ----
    const int w    = tid >> 5;
    const int lane = tid & 31;
    const int j0   = w * 4;

    float acc[4][4];
    #pragma unroll
    for (int c = 0; c < 4; ++c) {
        const int l = lane + 32 * c;
        const float b = ps[l * P_ROW + F_DIM];   // bias
        #pragma unroll
        for (int jj = 0; jj < 4; ++jj) acc[jj][c] = b;
    }

    #pragma unroll 4
    for (int k = 0; k < F_DIM; ++k) {
        float xv[4];
        #pragma unroll
        for (int jj = 0; jj < 4; ++jj)
            xv[jj] = xs[(j0 + jj) * F_DIM + k];          // warp-broadcast LDS
        float wv[4];
        #pragma unroll
        for (int c = 0; c < 4; ++c)
            wv[c] = ps[(lane + 32 * c) * P_ROW + k];     // stride 129 -> conflict-free
        #pragma unroll
        for (int jj = 0; jj < 4; ++jj)
            #pragma unroll
            for (int c = 0; c < 4; ++c)
                acc[jj][c] = fmaf(xv[jj], wv[c], acc[jj][c]);
    }

    // ---- write out[i, j, l] ----
    float* o = out + (size_t)i * X_SZ;
    #pragma unroll
    for (int jj = 0; jj < 4; ++jj)
        #pragma unroll
        for (int c = 0; c < 4; ++c)
            o[(j0 + jj) * F_DIM + (lane + 32 * c)] = acc[jj][c];
}

extern "C" void kernel_launch(void* const* d_in, const int* in_sizes, int n_in,
                              void* d_out, int out_size)
{
    const float* x      = (const float*)d_in[0];   // [8192,32,128] f32
    const int*   inds   = (const int*)d_in[1];     // [8192] int32 (JAX x64 off)
    const float* params = (const float*)d_in[2];   // [4096,128,129] f32
    float*       out    = (float*)d_out;           // [8192,32,128] f32

    (void)in_sizes; (void)n_in; (void)out_size;

    static_assert(SMEM_FLOATS * 4 == 82432, "smem size");
    cudaFuncSetAttribute(multidense_kernel,
                         cudaFuncAttributeMaxDynamicSharedMemorySize,
                         SMEM_FLOATS * 4);

    multidense_kernel<<<I_TOT, 256, SMEM_FLOATS * 4>>>(x, inds, params, out);
}

// round 6
// speedup vs baseline: 1.0209x; 1.0209x over previous
#include <cuda_runtime.h>
#include <cuda_bf16.h>
#include <cstdint>

// MultiDense: out[i,j,l] = sum_k x[i,j,k] * W[inds[i],l,k] + b[inds[i],l]
// I=8192, J=32, K=L=128. params row stride 129 (128 weights + bias).
// FFMA2 (fma.rn.f32x2) packed over j-pairs; x transposed in smem for vector broadcasts.

constexpr int I_TOT = 8192;
constexpr int J_DIM = 32;
constexpr int F_DIM = 128;
constexpr int N_NODES = 4096;
constexpr int P_ROW = 129;
constexpr int P_SZ  = F_DIM * P_ROW;        // 16512 floats
constexpr int X_SZ  = J_DIM * F_DIM;        // 4096 floats
constexpr int XT_STRIDE = 32;               // xT row: 32 floats (128B, 16B-aligned)
constexpr int SMEM_FLOATS = P_SZ + F_DIM * XT_STRIDE;   // 16512 + 4096 = 20608 -> 82432 B

using ull = unsigned long long;

__device__ __forceinline__ ull pack2(float a, float b) {
    ull r; asm("mov.b64 %0, {%1, %2};" : "=l"(r) : "f"(a), "f"(b)); return r;
}
__device__ __forceinline__ void unpack2(float& a, float& b, ull v) {
    asm("mov.b64 {%0, %1}, %2;" : "=f"(a), "=f"(b) : "l"(v));
}
__device__ __forceinline__ void fma2(ull& d, ull a, ull b) {
    asm("fma.rn.f32x2 %0, %1, %2, %0;" : "+l"(d) : "l"(a), "l"(b));
}

__global__ void __launch_bounds__(256, 2)
multidense_kernel(const float* __restrict__ x,
                  const int* __restrict__ inds,
                  const float* __restrict__ params,
                  float* __restrict__ out)
{
    extern __shared__ float smem[];
    float* ps = smem;                 // [128][129] gathered weights+bias
    float* xT = smem + P_SZ;          // [128][32]  transposed x tile (k-major)

    const int i    = blockIdx.x;
    const int tid  = threadIdx.x;
    const int lane = tid & 31;
    const int w    = tid >> 5;

    int node = inds[i];
    node = min(max(node, 0), N_NODES - 1);

    // ---- stage params (float4; base 16B-aligned: 16512 % 4 == 0) ----
    {
        const float4* src = reinterpret_cast<const float4*>(params + (size_t)node * P_SZ);
        float4* dst = reinterpret_cast<float4*>(ps);
        #pragma unroll 4
        for (int t = tid; t < P_SZ / 4; t += 256) dst[t] = src[t];
    }

    // ---- stage x transposed: xT[k][j] ----
    // thread: j = lane, k-quad = w + 8m  -> STS addr (4kq+q)*32 + lane: banks = lane, conflict-free
    {
        const float4* src = reinterpret_cast<const float4*>(x + (size_t)i * X_SZ);
        #pragma unroll
        for (int m = 0; m < 4; ++m) {
            const int kq = w + 8 * m;
            float4 v = src[lane * (F_DIM / 4) + kq];
            xT[(4 * kq + 0) * XT_STRIDE + lane] = v.x;
            xT[(4 * kq + 1) * XT_STRIDE + lane] = v.y;
            xT[(4 * kq + 2) * XT_STRIDE + lane] = v.z;
            xT[(4 * kq + 3) * XT_STRIDE + lane] = v.w;
        }
    }
    __syncthreads();

    // ---- compute: warp tile = 8 j  x  64 l ----
    // warp w: j0 = (w>>1)*8,  l = (w&1)*64 + lane + 32c (c in {0,1})
    const int j0 = (w >> 1) * 8;
    const int l0 = (w & 1) * 64 + lane;

    const float* __restrict__ wr0 = ps + (size_t)l0 * P_ROW;          // weight row l0
    const float* __restrict__ wr1 = ps + (size_t)(l0 + 32) * P_ROW;   // weight row l0+32

    ull acc[4][2];   // [j-pair][c], lanes = (j0+2jp, j0+2jp+1)
    {
        const float b0 = wr0[F_DIM];
        const float b1 = wr1[F_DIM];
        const ull pb0 = pack2(b0, b0);
        const ull pb1 = pack2(b1, b1);
        #pragma unroll
        for (int jp = 0; jp < 4; ++jp) { acc[jp][0] = pb0; acc[jp][1] = pb1; }
    }

    #pragma unroll 4
    for (int k = 0; k < F_DIM; ++k) {
        // 8 x-values for this warp's j-block: two 16B broadcast loads
        const float4 a0 = *reinterpret_cast<const float4*>(xT + k * XT_STRIDE + j0);
        const float4 a1 = *reinterpret_cast<const float4*>(xT + k * XT_STRIDE + j0 + 4);
        ull xp[4];
        xp[0] = pack2(a0.x, a0.y);
        xp[1] = pack2(a0.z, a0.w);
        xp[2] = pack2(a1.x, a1.y);
        xp[3] = pack2(a1.z, a1.w);

        const float w0 = wr0[k];                 // stride-129 rows: conflict-free LDS
        const float w1 = wr1[k];
        const ull wp0 = pack2(w0, w0);
        const ull wp1 = pack2(w1, w1);

        #pragma unroll
        for (int jp = 0; jp < 4; ++jp) {
            fma2(acc[jp][0], xp[jp], wp0);
            fma2(acc[jp][1], xp[jp], wp1);
        }
    }

    // ---- write out[i, j, l] (each STG instr: fixed j row, lane-contiguous l) ----
    float* o = out + (size_t)i * X_SZ;
    #pragma unroll
    for (int jp = 0; jp < 4; ++jp) {
        #pragma unroll
        for (int c = 0; c < 2; ++c) {
            float lo, hi;
            unpack2(lo, hi, acc[jp][c]);
            const int l = l0 + 32 * c;
            o[(j0 + 2 * jp + 0) * F_DIM + l] = lo;
            o[(j0 + 2 * jp + 1) * F_DIM + l] = hi;
        }
    }
}

extern "C" void kernel_launch(void* const* d_in, const int* in_sizes, int n_in,
                              void* d_out, int out_size)
{
    const float* x      = (const float*)d_in[0];   // [8192,32,128] f32
    const int*   inds   = (const int*)d_in[1];     // [8192] int32
    const float* params = (const float*)d_in[2];   // [4096,128,129] f32
    float*       out    = (float*)d_out;           // [8192,32,128] f32

    (void)in_sizes; (void)n_in; (void)out_size;

    cudaFuncSetAttribute(multidense_kernel,
                         cudaFuncAttributeMaxDynamicSharedMemorySize,
                         SMEM_FLOATS * 4);

    multidense_kernel<<<I_TOT, 256, SMEM_FLOATS * 4>>>(x, inds, params, out);
}